// round 11
// baseline (speedup 1.0000x reference)
#include <cuda_runtime.h>
#include <cstdint>

// out[b, n, :] = (cnn[b] @ Wkv[:, 768:1536]) @ Wp + bp   (independent of n)
// image_patches and Wq are dead: softmax over kv_len=1 -> attn == 1.
//
// 3 launches:
//   gemm1: 384 CTAs x 512 thr (12 n-tiles x 32 k-splits of 64), red.v4 -> g_v
//          (g_v == 0 on entry: static init call 1, re-zeroed by bcast each
//          call). Prologue: g_y = bias.
//   gemm2: 192 CTAs x 512 thr (12 n-tiles x 16 k-splits of 48), red.v4 -> g_y.
//   bcast: 576 CTAs x 8 TMA bulk stores of 24 KB; zeroes g_v at end.

#define B_SZ   64
#define N_SEQ  576
#define C_DIM  768
#define K1     2048
#define LDKV   1536

#define NT1    12              // gemm1: 12 n-tiles of 64
#define KS1    32              // gemm1: 32 k-splits of 64 -> 384 blocks
#define KC1    64
#define NT2    12              // gemm2: 12 n-tiles of 64
#define KS2    16              // gemm2: 16 k-splits of 48 -> 192 blocks
#define KC2    48

__device__ float g_v[B_SZ * C_DIM];   // zero on entry to every call
__device__ float g_y[B_SZ * C_DIM];   // set to bias by gemm1 every call

// ---- packed f32x2 (FFMA2) ----
__device__ __forceinline__ unsigned long long pack2(float x) {
    unsigned long long r; unsigned xi = __float_as_uint(x);
    asm("mov.b64 %0, {%1, %1};" : "=l"(r) : "r"(xi));
    return r;
}
__device__ __forceinline__ void fma2(unsigned long long& d,
                                     unsigned long long a, unsigned long long b) {
    asm("fma.rn.f32x2 %0, %1, %2, %0;" : "+l"(d) : "l"(a), "l"(b));
}
__device__ __forceinline__ float2 u2f(unsigned long long u) {
    float2 f; asm("mov.b64 {%0, %1}, %2;" : "=f"(f.x), "=f"(f.y) : "l"(u));
    return f;
}
// Vector reduction: 1 LTS atomic op for 4 floats (sm_90+).
__device__ __forceinline__ void redg_add4(float* p, float a, float b, float c, float d) {
    asm volatile("red.global.add.v4.f32 [%0], {%1, %2, %3, %4};"
                 :: "l"(p), "f"(a), "f"(b), "f"(c), "f"(d) : "memory");
}
__device__ __forceinline__ uint32_t smem_u32(const void* p) {
    uint32_t a;
    asm("{ .reg .u64 t; cvta.to.shared.u64 t, %1; cvt.u32.u64 %0, t; }" : "=r"(a) : "l"(p));
    return a;
}

// ---------------------------------------------------------------------------
// 512-thread double-buffered 64x64 tile GEMM body; 8 outputs/thread (2m x 4n).
// Warps 0-7 load the A tile, warps 8-15 load the B tile (divergence-free).
// Inner k-step per thread: LDS.64 (A) + LDS.128 (B) + 2 packs + 4 FFMA2.
// ---------------------------------------------------------------------------
template<int KCHUNK>
__device__ __forceinline__ void gemm_body512(
    const float* __restrict__ A, int lda,
    const float* __restrict__ Bm, int ldb,
    float (*As)[68], float (*Bs)[64],
    unsigned long long acc[2][2])
{
    const int tid = threadIdx.x;
    const int tx = tid & 15;          // n group (4 cols)
    const int ty = tid >> 4;          // m group (2 rows), 0..31
    const bool isA = tid < 256;
    const int m  = tid >> 2, kq = (tid & 3) * 4;            // A-loader coords
    const int t  = tid - 256;
    const int kb = t >> 4,  n4 = (t & 15) * 4;              // B-loader coords

    float4 reg = isA ? *(const float4*)&A[m * lda + kq]
                     : *(const float4*)&Bm[kb * ldb + n4];

    #pragma unroll
    for (int kt = 0; kt < KCHUNK; kt += 16) {
        if (isA) {
            As[kq + 0][m] = reg.x; As[kq + 1][m] = reg.y;
            As[kq + 2][m] = reg.z; As[kq + 3][m] = reg.w;
        } else {
            *(float4*)&Bs[kb][n4] = reg;
        }
        __syncthreads();

        if (kt + 16 < KCHUNK) {
            reg = isA ? *(const float4*)&A[m * lda + kt + 16 + kq]
                      : *(const float4*)&Bm[(kt + 16 + kb) * ldb + n4];
        }

        #pragma unroll
        for (int k = 0; k < 16; ++k) {
            float2 a = *(const float2*)&As[k][ty * 2];
            ulonglong2 b = *(const ulonglong2*)&Bs[k][tx * 4];
            unsigned long long a0 = pack2(a.x), a1 = pack2(a.y);
            fma2(acc[0][0], a0, b.x); fma2(acc[0][1], a0, b.y);
            fma2(acc[1][0], a1, b.x); fma2(acc[1][1], a1, b.y);
        }
        __syncthreads();
    }
}

// GEMM1: cnn[64,2048] @ Wkv[:,768:1536], 384 blocks x 512 thr, red.v4 -> g_v.
// Prologue (first 192 blocks): g_y = bias.
__global__ void __launch_bounds__(512, 2)
gemm1_kernel(const float* __restrict__ cnn, const float* __restrict__ Wkv,
             const float* __restrict__ bp)
{
    __shared__ float As[16][68];
    __shared__ float Bs[16][64];

    const int tid = threadIdx.x;
    if (blockIdx.x < 192 && tid < 64) {
        int idx = blockIdx.x * 64 + tid;                  // 12288 float4 of g_y
        ((float4*)g_y)[idx] = ((const float4*)bp)[idx % (C_DIM / 4)];
    }

    int ntile = blockIdx.x % NT1;
    int split = blockIdx.x / NT1;
    int n0 = ntile * 64;

    unsigned long long acc[2][2] = {{0ull, 0ull}, {0ull, 0ull}};

    gemm_body512<KC1>(cnn + split * KC1, K1,
                      Wkv + (size_t)(split * KC1) * LDKV + C_DIM + n0, LDKV,
                      As, Bs, acc);

    const int tx = tid & 15, ty = tid >> 4;
    #pragma unroll
    for (int i = 0; i < 2; ++i) {
        float2 f0 = u2f(acc[i][0]);
        float2 f1 = u2f(acc[i][1]);
        redg_add4(g_v + (ty * 2 + i) * C_DIM + n0 + tx * 4,
                  f0.x, f0.y, f1.x, f1.y);
    }
}

// GEMM2: v[64,768] @ Wp, 192 blocks x 512 thr, red.v4 into g_y (bias preloaded).
__global__ void __launch_bounds__(512, 2)
gemm2_kernel(const float* __restrict__ Wp)
{
    __shared__ float As[16][68];
    __shared__ float Bs[16][64];

    const int tid = threadIdx.x;
    int ntile = blockIdx.x % NT2;
    int split = blockIdx.x / NT2;
    int n0 = ntile * 64;

    unsigned long long acc[2][2] = {{0ull, 0ull}, {0ull, 0ull}};

    gemm_body512<KC2>(g_v + split * KC2, C_DIM,
                      Wp + (size_t)(split * KC2) * C_DIM + n0, C_DIM,
                      As, Bs, acc);

    const int tx = tid & 15, ty = tid >> 4;
    #pragma unroll
    for (int i = 0; i < 2; ++i) {
        float2 f0 = u2f(acc[i][0]);
        float2 f1 = u2f(acc[i][1]);
        redg_add4(g_y + (ty * 2 + i) * C_DIM + n0 + tx * 4,
                  f0.x, f0.y, f1.x, f1.y);
    }
}

// Broadcast g_y over N=576 via TMA bulk stores; zero g_v for the next call.
// 576 blocks x 512 threads: b = bx/9, 64 rows per block; stage 8 replicated
// rows (24 KB) once, then 8 bulk stores of 24 KB (8 rows each).
__global__ void __launch_bounds__(512)
bcast_kernel(float* __restrict__ out)
{
    __shared__ __align__(16) float ys[8 * C_DIM];   // 24 KB

    int b     = blockIdx.x / 9;
    int chunk = blockIdx.x % 9;
    const int tid = threadIdx.x;

    const float4* ysrc = (const float4*)(g_y + b * C_DIM);
    #pragma unroll
    for (int i = tid; i < 8 * (C_DIM / 4); i += 512)
        ((float4*)ys)[i] = ysrc[i % (C_DIM / 4)];
    __syncthreads();
    asm volatile("fence.proxy.async.shared::cta;" ::: "memory");

    if (tid < 8) {
        uint32_t s = smem_u32(ys);
        float* g = out + ((size_t)b * N_SEQ + chunk * 64 + tid * 8) * C_DIM;
        asm volatile("cp.async.bulk.global.shared::cta.bulk_group [%0], [%1], %2;"
                     :: "l"(g), "r"(s), "n"(8 * C_DIM * 4) : "memory");
        asm volatile("cp.async.bulk.commit_group;" ::: "memory");
        asm volatile("cp.async.bulk.wait_group 0;" ::: "memory");
    }

    // zero g_v for the next call (first 192 blocks cover 12288 float4)
    if (blockIdx.x < 192 && tid < 64) {
        ((float4*)g_v)[blockIdx.x * 64 + tid] = make_float4(0.f, 0.f, 0.f, 0.f);
    }
}

extern "C" void kernel_launch(void* const* d_in, const int* in_sizes, int n_in,
                              void* d_out, int out_size)
{
    (void)in_sizes; (void)n_in; (void)out_size;
    // Inputs: image_patches, cnn_feature_vector, Wq, Wkv, Wp, bp
    const float* cnn = (const float*)d_in[1];
    const float* Wkv = (const float*)d_in[3];
    const float* Wp  = (const float*)d_in[4];
    const float* bp  = (const float*)d_in[5];
    float* out = (float*)d_out;

    gemm1_kernel<<<NT1 * KS1, 512>>>(cnn, Wkv, bp);   // 384 blocks
    gemm2_kernel<<<NT2 * KS2, 512>>>(Wp);             // 192 blocks
    bcast_kernel<<<B_SZ * 9, 512>>>(out);             // 576 blocks
}

// round 12
// speedup vs baseline: 1.1096x; 1.1096x over previous
#include <cuda_runtime.h>
#include <cstdint>

// out[b, n, :] = (cnn[b] @ Wkv[:, 768:1536]) @ Wp + bp   (independent of n)
// image_patches and Wq are dead: softmax over kv_len=1 -> attn == 1.
//
// 3 launches:
//   gemm1: 384 CTAs x 256 thr (12 n-tiles x 32 k-splits of 64). Whole K-chunk
//          staged in smem in ONE phase (8x LDG.128/thread), one sync, then a
//          64-step FFMA2 loop. red.v4 epilogue -> g_v (zero on entry: static
//          init call 1, re-zeroed by bcast each call). Prologue: g_y = bias.
//   gemm2: 192 CTAs x 256 thr (12 n-tiles x 16 k-splits of 48), same scheme,
//          red.v4 -> bias-preloaded g_y.
//   bcast: 576 CTAs x 8 TMA bulk stores of 24 KB; zeroes g_v at end.

#define B_SZ   64
#define N_SEQ  576
#define C_DIM  768
#define K1     2048
#define LDKV   1536

#define NT1    12              // gemm1: 12 n-tiles of 64
#define KS1    32              // gemm1: 32 k-splits of 64 -> 384 blocks
#define KC1    64
#define NT2    12              // gemm2: 12 n-tiles of 64
#define KS2    16              // gemm2: 16 k-splits of 48 -> 192 blocks
#define KC2    48

__device__ float g_v[B_SZ * C_DIM];   // zero on entry to every call
__device__ float g_y[B_SZ * C_DIM];   // set to bias by gemm1 every call

// ---- packed f32x2 (FFMA2) ----
__device__ __forceinline__ unsigned long long pack2(float x) {
    unsigned long long r; unsigned xi = __float_as_uint(x);
    asm("mov.b64 %0, {%1, %1};" : "=l"(r) : "r"(xi));
    return r;
}
__device__ __forceinline__ void fma2(unsigned long long& d,
                                     unsigned long long a, unsigned long long b) {
    asm("fma.rn.f32x2 %0, %1, %2, %0;" : "+l"(d) : "l"(a), "l"(b));
}
__device__ __forceinline__ float2 u2f(unsigned long long u) {
    float2 f; asm("mov.b64 {%0, %1}, %2;" : "=f"(f.x), "=f"(f.y) : "l"(u));
    return f;
}
// Vector reduction: 1 LTS atomic op for 4 floats (sm_90+).
__device__ __forceinline__ void redg_add4(float* p, float a, float b, float c, float d) {
    asm volatile("red.global.add.v4.f32 [%0], {%1, %2, %3, %4};"
                 :: "l"(p), "f"(a), "f"(b), "f"(c), "f"(d) : "memory");
}
__device__ __forceinline__ uint32_t smem_u32(const void* p) {
    uint32_t a;
    asm("{ .reg .u64 t; cvta.to.shared.u64 t, %1; cvt.u32.u64 %0, t; }" : "=r"(a) : "l"(p));
    return a;
}

// ---------------------------------------------------------------------------
// Single-phase 64x64 tile GEMM: stage FULL K-chunk (KCHUNK x 64 both operands)
// in smem with batched LDG.128, one __syncthreads, then an uninterrupted
// KCHUNK-step FFMA2 loop (4m x 4n per thread, 256 threads).
// ---------------------------------------------------------------------------
template<int KCHUNK>
__device__ __forceinline__ void gemm_tile_1phase(
    const float* __restrict__ A, int lda,     // A[64 x KCHUNK], row-major
    const float* __restrict__ Bm, int ldb,    // B[KCHUNK x 64], row-major
    float (*As)[68],                          // [KCHUNK][68] transposed A
    float (*Bs)[64],                          // [KCHUNK][64]
    unsigned long long acc[4][2])
{
    const int tid = threadIdx.x;
    constexpr int NV = (64 * KCHUNK) / 4;     // float4 count per operand

    // Batched loads into registers first (MLP = 2*NV/256 per thread).
    float4 aR[NV / 256], bR[NV / 256];
    #pragma unroll
    for (int i = 0; i < NV / 256; ++i) {
        int idx = tid + i * 256;
        // A: idx -> (m, kq) ; row m has KCHUNK/4 float4s
        int am = idx / (KCHUNK / 4);
        int ak = (idx % (KCHUNK / 4)) * 4;
        aR[i] = *(const float4*)&A[am * lda + ak];
        // B: idx -> (k, n4) ; row k has 16 float4s
        int bk = idx >> 4;
        int bn = (idx & 15) * 4;
        bR[i] = *(const float4*)&Bm[bk * ldb + bn];
    }
    #pragma unroll
    for (int i = 0; i < NV / 256; ++i) {
        int idx = tid + i * 256;
        int am = idx / (KCHUNK / 4);
        int ak = (idx % (KCHUNK / 4)) * 4;
        As[ak + 0][am] = aR[i].x; As[ak + 1][am] = aR[i].y;
        As[ak + 2][am] = aR[i].z; As[ak + 3][am] = aR[i].w;
        int bk = idx >> 4;
        int bn = (idx & 15) * 4;
        *(float4*)&Bs[bk][bn] = bR[i];
    }
    __syncthreads();

    const int tx = tid & 15, ty = tid >> 4;
    #pragma unroll 16
    for (int k = 0; k < KCHUNK; ++k) {
        float4 a = *(const float4*)&As[k][ty * 4];
        ulonglong2 b = *(const ulonglong2*)&Bs[k][tx * 4];
        unsigned long long a0 = pack2(a.x), a1 = pack2(a.y);
        unsigned long long a2 = pack2(a.z), a3 = pack2(a.w);
        fma2(acc[0][0], a0, b.x); fma2(acc[0][1], a0, b.y);
        fma2(acc[1][0], a1, b.x); fma2(acc[1][1], a1, b.y);
        fma2(acc[2][0], a2, b.x); fma2(acc[2][1], a2, b.y);
        fma2(acc[3][0], a3, b.x); fma2(acc[3][1], a3, b.y);
    }
}

// GEMM1: cnn[64,2048] @ Wkv[:,768:1536], 384 blocks, red.v4 epilogue -> g_v.
// Prologue (first 192 blocks): g_y = bias.
__global__ void __launch_bounds__(256, 2)
gemm1_kernel(const float* __restrict__ cnn, const float* __restrict__ Wkv,
             const float* __restrict__ bp)
{
    __shared__ float As[KC1][68];   // 17.4 KB
    __shared__ float Bs[KC1][64];   // 16 KB

    const int tid = threadIdx.x;
    if (blockIdx.x < 192 && tid < 64) {
        int idx = blockIdx.x * 64 + tid;                  // 12288 float4 of g_y
        ((float4*)g_y)[idx] = ((const float4*)bp)[idx % (C_DIM / 4)];
    }

    int ntile = blockIdx.x % NT1;
    int split = blockIdx.x / NT1;
    int n0 = ntile * 64;

    unsigned long long acc[4][2];
    #pragma unroll
    for (int i = 0; i < 4; ++i) { acc[i][0] = 0ull; acc[i][1] = 0ull; }

    gemm_tile_1phase<KC1>(cnn + split * KC1, K1,
                          Wkv + (size_t)(split * KC1) * LDKV + C_DIM + n0, LDKV,
                          As, Bs, acc);

    const int tx = tid & 15, ty = tid >> 4;
    #pragma unroll
    for (int i = 0; i < 4; ++i) {
        float2 f0 = u2f(acc[i][0]);
        float2 f1 = u2f(acc[i][1]);
        redg_add4(g_v + (ty * 4 + i) * C_DIM + n0 + tx * 4,
                  f0.x, f0.y, f1.x, f1.y);
    }
}

// GEMM2: v[64,768] @ Wp, 192 blocks, red.v4 epilogue into g_y (bias preloaded).
__global__ void __launch_bounds__(256, 2)
gemm2_kernel(const float* __restrict__ Wp)
{
    __shared__ float As[KC2][68];   // 13 KB
    __shared__ float Bs[KC2][64];   // 12 KB

    const int tid = threadIdx.x;
    int ntile = blockIdx.x % NT2;
    int split = blockIdx.x / NT2;
    int n0 = ntile * 64;

    unsigned long long acc[4][2];
    #pragma unroll
    for (int i = 0; i < 4; ++i) { acc[i][0] = 0ull; acc[i][1] = 0ull; }

    gemm_tile_1phase<KC2>(g_v + split * KC2, C_DIM,
                          Wp + (size_t)(split * KC2) * C_DIM + n0, C_DIM,
                          As, Bs, acc);

    const int tx = tid & 15, ty = tid >> 4;
    #pragma unroll
    for (int i = 0; i < 4; ++i) {
        float2 f0 = u2f(acc[i][0]);
        float2 f1 = u2f(acc[i][1]);
        redg_add4(g_y + (ty * 4 + i) * C_DIM + n0 + tx * 4,
                  f0.x, f0.y, f1.x, f1.y);
    }
}

// Broadcast g_y over N=576 via TMA bulk stores; zero g_v for the next call.
// 576 blocks x 512 threads: b = bx/9, 64 rows per block; stage 8 replicated
// rows (24 KB) once, then 8 bulk stores of 24 KB (8 rows each).
__global__ void __launch_bounds__(512)
bcast_kernel(float* __restrict__ out)
{
    __shared__ __align__(16) float ys[8 * C_DIM];   // 24 KB

    int b     = blockIdx.x / 9;
    int chunk = blockIdx.x % 9;
    const int tid = threadIdx.x;

    const float4* ysrc = (const float4*)(g_y + b * C_DIM);
    #pragma unroll
    for (int i = tid; i < 8 * (C_DIM / 4); i += 512)
        ((float4*)ys)[i] = ysrc[i % (C_DIM / 4)];
    __syncthreads();
    asm volatile("fence.proxy.async.shared::cta;" ::: "memory");

    if (tid < 8) {
        uint32_t s = smem_u32(ys);
        float* g = out + ((size_t)b * N_SEQ + chunk * 64 + tid * 8) * C_DIM;
        asm volatile("cp.async.bulk.global.shared::cta.bulk_group [%0], [%1], %2;"
                     :: "l"(g), "r"(s), "n"(8 * C_DIM * 4) : "memory");
        asm volatile("cp.async.bulk.commit_group;" ::: "memory");
        asm volatile("cp.async.bulk.wait_group 0;" ::: "memory");
    }

    // zero g_v for the next call (first 192 blocks cover 12288 float4)
    if (blockIdx.x < 192 && tid < 64) {
        ((float4*)g_v)[blockIdx.x * 64 + tid] = make_float4(0.f, 0.f, 0.f, 0.f);
    }
}

extern "C" void kernel_launch(void* const* d_in, const int* in_sizes, int n_in,
                              void* d_out, int out_size)
{
    (void)in_sizes; (void)n_in; (void)out_size;
    // Inputs: image_patches, cnn_feature_vector, Wq, Wkv, Wp, bp
    const float* cnn = (const float*)d_in[1];
    const float* Wkv = (const float*)d_in[3];
    const float* Wp  = (const float*)d_in[4];
    const float* bp  = (const float*)d_in[5];
    float* out = (float*)d_out;

    gemm1_kernel<<<NT1 * KS1, 256>>>(cnn, Wkv, bp);   // 384 blocks
    gemm2_kernel<<<NT2 * KS2, 256>>>(Wp);             // 192 blocks
    bcast_kernel<<<B_SZ * 9, 512>>>(out);             // 576 blocks
}